// round 15
// baseline (speedup 1.0000x reference)
#include <cuda_runtime.h>
#include <cuda_bf16.h>
#include <cstdint>

#define DEVINL __device__ __forceinline__

constexpr int B_ = 8;
constexpr int N_ = 4096;

// ---------------- device scratch (no allocations allowed) ----------------
__device__ uint32_t d_Bfrag[(size_t)B_ * 131072];        // fragment-major mu_pre (GEMM B operand)
__device__ uint32_t d_mu_pool_b16[(size_t)B_ * N_ * 32]; // [B][N][32 kwords] bf16x2 dim-pairs
__device__ uint32_t d_mu_b16[(size_t)B_ * N_ * 32];      // final mu, bf16x2 dim-pairs
__device__ float    d_partial[B_ * 64 * 64];             // per-64-node-block pooled partials
__device__ uint32_t d_wT[6 * 2304];                      // 6 layers W^T bf16, padded stride 36
__device__ uint32_t d_wTq[1152];                         // qregW lower half W^T, stride 36

// ---------------- helpers ----------------
DEVINL uint32_t smem_u32(const void* p) {
    uint32_t a;
    asm("{ .reg .u64 t; cvta.to.shared.u64 t, %1; cvt.u32.u64 %0, t; }" : "=r"(a) : "l"(p));
    return a;
}
DEVINL void cp_async16(uint32_t dst, const void* src) {
    asm volatile("cp.async.cg.shared.global [%0], [%1], 16;\n" :: "r"(dst), "l"(src));
}
DEVINL void cp_commit() { asm volatile("cp.async.commit_group;\n" ::); }
#define CP_WAIT(n) asm volatile("cp.async.wait_group %0;\n" :: "n"(n))

DEVINL uint32_t pack_bf16x2(float lo, float hi) {
    __nv_bfloat162 v = __floats2bfloat162_rn(lo, hi);
    return *(uint32_t*)&v;
}

// mma.sync m16n8k16 bf16 (A row-major, B col-major), fp32 accumulate.
DEVINL void mma_bf16(float* d, const uint32_t* a, const uint32_t* b) {
    asm volatile(
        "mma.sync.aligned.m16n8k16.row.col.f32.bf16.bf16.f32 "
        "{%0,%1,%2,%3}, {%4,%5,%6,%7}, {%8,%9}, {%0,%1,%2,%3};"
        : "+f"(d[0]), "+f"(d[1]), "+f"(d[2]), "+f"(d[3])
        : "r"(a[0]), "r"(a[1]), "r"(a[2]), "r"(a[3]), "r"(b[0]), "r"(b[1]));
}

// ---------------- register-resident 64-wide layer primitives ----------------
// w[j][0] = rows lr, cols j*8+2lc..+1 (bf16x2); w[j][1] = rows lr+8.
// Weight tables use stride 36 words: (j*8+lr)*36 + kt*8+lc.

DEVINL void init_bias(float acc[8][4], const float* __restrict__ bias, int lc) {
#pragma unroll
    for (int j = 0; j < 8; j++) {
        float b0 = bias[j * 8 + 2 * lc], b1 = bias[j * 8 + 2 * lc + 1];
        acc[j][0] = b0; acc[j][1] = b1; acc[j][2] = b0; acc[j][3] = b1;
    }
}
DEVINL void pack_words(const float acc[8][4], uint32_t w[8][2], bool relu) {
#pragma unroll
    for (int j = 0; j < 8; j++) {
        float a0 = acc[j][0], a1 = acc[j][1], a2 = acc[j][2], a3 = acc[j][3];
        if (relu) { a0 = fmaxf(a0, 0.f); a1 = fmaxf(a1, 0.f); a2 = fmaxf(a2, 0.f); a3 = fmaxf(a3, 0.f); }
        w[j][0] = pack_bf16x2(a0, a1);
        w[j][1] = pack_bf16x2(a2, a3);
    }
}
DEVINL void layer_mma(float acc[8][4], const uint32_t w[8][2],
                      const uint32_t* __restrict__ wT, int lr, int lc) {
#pragma unroll
    for (int kt = 0; kt < 4; kt++) {
        uint32_t a[4] = { w[2 * kt][0], w[2 * kt][1], w[2 * kt + 1][0], w[2 * kt + 1][1] };
#pragma unroll
        for (int j = 0; j < 8; j++) {
            uint32_t bb[2];
            bb[0] = wT[(j * 8 + lr) * 36 + kt * 8 + lc];
            bb[1] = wT[(j * 8 + lr) * 36 + kt * 8 + lc + 4];
            mma_bf16(acc[j], a, bb);
        }
    }
}

// ============ kernel 0: convert all layer weights to bf16 W^T (stride 36) ============
__global__ void wprep_kernel(
    const float* __restrict__ preW, const float* __restrict__ postW,
    const float* __restrict__ mu2W, const float* __restrict__ q2W,
    const float* __restrict__ qregW)
{
    int gid = blockIdx.x * 256 + threadIdx.x;
    int gstride = gridDim.x * 256;
    for (int idx = gid; idx < 6 * 2304; idx += gstride) {
        int l = idx / 2304, r = idx % 2304, dout = r / 36, col = r % 36;
        uint32_t v = 0;
        if (col < 32) {
            const float* W;
            switch (l) {
                case 0: W = preW;         break;
                case 1: W = preW + 4096;  break;
                case 2: W = postW;        break;
                case 3: W = postW + 4096; break;
                case 4: W = mu2W;         break;
                default: W = q2W;         break;
            }
            v = pack_bf16x2(W[(2 * col) * 64 + dout], W[(2 * col + 1) * 64 + dout]);
        }
        d_wT[idx] = v;
    }
    for (int idx = gid; idx < 1152; idx += gstride) {
        int rh = idx / 36, col = idx % 36;
        uint32_t v = 0;
        if (col < 32)
            v = pack_bf16x2(qregW[(64 + 2 * col) * 32 + rh],
                            qregW[(64 + 2 * col + 1) * 32 + rh]);
        d_wTq[idx] = v;
    }
}

// ============ kernel 1: mu0 -> 2 pre layers -> fragment-major d_Bfrag ============
// d_Bfrag line layout (per chunk c): [j][slot][kt][h]  -> one LDG.128 per j in gemm
__global__ void __launch_bounds__(128) prep_kernel(
    const float* __restrict__ xv, const int* __restrict__ mask,
    const float* __restrict__ mu1, const float* __restrict__ preb)
{
    __shared__ uint32_t sS[64 * 36];        // [node][kword] staging, stride 36
    __shared__ uint32_t sW[2 * 2304];       // layers 0,1 weights
    int b  = blockIdx.x >> 6;
    int n0 = (blockIdx.x & 63) << 6;
    int tid = threadIdx.x, wid = tid >> 5, lane = tid & 31;
    int lr = lane >> 2, lc = lane & 3;
    int rl0 = wid * 16 + lr;
    int row0 = n0 + rl0;

    for (int i = tid; i < 2 * 2304 / 4; i += 128)
        ((uint4*)sW)[i] = ((const uint4*)d_wT)[i];

    float xv0 = xv[b * N_ + row0],     xv8 = xv[b * N_ + row0 + 8];
    float mv0 = (float)mask[b * N_ + row0], mv8 = (float)mask[b * N_ + row0 + 8];

    uint32_t w[8][2];
#pragma unroll
    for (int j = 0; j < 8; j++) {
        int c0 = j * 8 + 2 * lc;
        float u0 = mu1[c0], u1 = mu1[c0 + 1];
        w[j][0] = pack_bf16x2(fmaxf(xv0 * u0, 0.f) * mv0, fmaxf(xv0 * u1, 0.f) * mv0);
        w[j][1] = pack_bf16x2(fmaxf(xv8 * u0, 0.f) * mv8, fmaxf(xv8 * u1, 0.f) * mv8);
    }
    __syncthreads();
    float acc[8][4];
    init_bias(acc, preb, lc);       layer_mma(acc, w, sW,        lr, lc); pack_words(acc, w, true);
    init_bias(acc, preb + 64, lc);  layer_mma(acc, w, sW + 2304, lr, lc); pack_words(acc, w, true);

#pragma unroll
    for (int j = 0; j < 8; j++) {
        sS[rl0 * 36 + j * 4 + lc]       = w[j][0];
        sS[(rl0 + 8) * 36 + j * 4 + lc] = w[j][1];
    }
    __syncthreads();

    // scatter to fragment-major layout; warp handles j = 2*wid, 2*wid+1
    int lrw = lane & 7, lcw = lane >> 3;
    int slot = lcw * 8 + lrw;
    int c0 = n0 >> 5;                     // first chunk covered by this block
#pragma unroll
    for (int cl = 0; cl < 2; cl++)
#pragma unroll
        for (int kt = 0; kt < 2; kt++)
#pragma unroll
            for (int h = 0; h < 2; h++)
#pragma unroll
                for (int jj = 0; jj < 2; jj++) {
                    int j  = wid * 2 + jj;
                    int dd = j * 8 + lrw;
                    int jp = cl * 16 + kt * 8 + lcw + 4 * h;   // local node-pair
                    uint32_t w0 = sS[(2 * jp) * 36 + (dd >> 1)];
                    uint32_t w1 = sS[(2 * jp + 1) * 36 + (dd >> 1)];
                    uint32_t out = __byte_perm(w0, w1, (dd & 1) ? 0x7632 : 0x5410);
                    d_Bfrag[(size_t)b * 131072 + (size_t)(c0 + cl) * 1024 +
                            j * 128 + slot * 4 + kt * 2 + h] = out;
                }
}

// ============ kernel 2: warp-decoupled bf16 GEMM, 16 warps/SM ============
// Each warp owns 16 M-rows: private 4-stage cp.async ring for A (pad-40,
// conflict-free); B fragments via ONE LDG.128 per j (L1 reuse across warps).
constexpr int A_STRIDE = 40;                        // words per row (160B)
constexpr int WSTAGE_WORDS = 16 * A_STRIDE;         // 640 words = 2560B per warp-stage
constexpr int GEMM_SMEM = 8 * 4 * WSTAGE_WORDS * 4; // 8 warps x 4 stages = 81920B

__global__ void __launch_bounds__(256, 2) gemm_kernel(
    const float* __restrict__ adj, const int* __restrict__ mask)
{
    extern __shared__ __align__(16) float smemf[];
    const uint32_t sm_base = smem_u32(smemf);
    int tid = threadIdx.x, wid = tid >> 5, lane = tid & 31;
    int b  = blockIdx.x >> 5;
    int m0 = (blockIdx.x & 31) << 7;
    const int wrow = wid * 16;
    const float* adjb = adj + (size_t)b * N_ * N_ + (size_t)(m0 + wrow) * N_;
    const uint32_t* bfb = d_Bfrag + (size_t)b * 131072;

    const uint32_t warpbase = sm_base + (uint32_t)(wid * 4 * WSTAGE_WORDS) * 4u;
    float* const warpf = smemf + wid * 4 * WSTAGE_WORDS;

    auto load_stage = [&](int slot, int chunk) {
        uint32_t base = warpbase + (uint32_t)(slot * WSTAGE_WORDS) * 4u;
        int kb = chunk * 32;
#pragma unroll
        for (int i = 0; i < 4; i++) {
            int idx = lane + i * 32;
            int row = idx >> 3, seg = idx & 7;
            cp_async16(base + (uint32_t)(row * A_STRIDE * 4 + seg * 16),
                       adjb + (size_t)row * N_ + kb + seg * 4);
        }
    };

    load_stage(0, 0); cp_commit();
    load_stage(1, 1); cp_commit();
    load_stage(2, 2); cp_commit();

    float acc[8][4];
#pragma unroll
    for (int j = 0; j < 8; j++)
#pragma unroll
        for (int r = 0; r < 4; r++) acc[j][r] = 0.0f;

    const int lr = lane >> 2, lc = lane & 3;
    const int bslot = lc * 8 + lr;        // fragment slot within a line

    for (int c = 0; c < 128; c++) {
        CP_WAIT(2);                       // this warp's chunk-c group done
        __syncwarp();                     // cross-lane visibility within warp
        if (c + 3 < 128) load_stage((c + 3) & 3, c + 3);
        cp_commit();

        const float* sA = warpf + (c & 3) * WSTAGE_WORDS;
        const uint32_t* bc = bfb + (size_t)c * 1024;
        uint32_t af0[4], af1[4];
        {
            float2 p0 = *(const float2*)&sA[(lr    ) * A_STRIDE + 2 * lc    ];
            float2 p1 = *(const float2*)&sA[(lr + 8) * A_STRIDE + 2 * lc    ];
            float2 p2 = *(const float2*)&sA[(lr    ) * A_STRIDE + 2 * lc + 8];
            float2 p3 = *(const float2*)&sA[(lr + 8) * A_STRIDE + 2 * lc + 8];
            af0[0] = pack_bf16x2(p0.x, p0.y);
            af0[1] = pack_bf16x2(p1.x, p1.y);
            af0[2] = pack_bf16x2(p2.x, p2.y);
            af0[3] = pack_bf16x2(p3.x, p3.y);
            p0 = *(const float2*)&sA[(lr    ) * A_STRIDE + 16 + 2 * lc    ];
            p1 = *(const float2*)&sA[(lr + 8) * A_STRIDE + 16 + 2 * lc    ];
            p2 = *(const float2*)&sA[(lr    ) * A_STRIDE + 16 + 2 * lc + 8];
            p3 = *(const float2*)&sA[(lr + 8) * A_STRIDE + 16 + 2 * lc + 8];
            af1[0] = pack_bf16x2(p0.x, p0.y);
            af1[1] = pack_bf16x2(p1.x, p1.y);
            af1[2] = pack_bf16x2(p2.x, p2.y);
            af1[3] = pack_bf16x2(p3.x, p3.y);
        }
#pragma unroll
        for (int j = 0; j < 8; j++) {
            uint4 bv = *(const uint4*)&bc[j * 128 + bslot * 4];
            uint32_t b0[2] = { bv.x, bv.y };
            uint32_t b1[2] = { bv.z, bv.w };
            mma_bf16(acc[j], af0, b0);
            mma_bf16(acc[j], af1, b1);
        }
    }

    // epilogue: mask, pack bf16, store kword layout [row][j*4+lc]
#pragma unroll
    for (int half = 0; half < 2; half++) {
        int row = m0 + wrow + lr + half * 8;
        float mv = (float)mask[b * N_ + row];
        uint32_t* dst = d_mu_pool_b16 + (size_t)(b * N_ + row) * 32;
#pragma unroll
        for (int j = 0; j < 8; j++)
            dst[j * 4 + lc] = pack_bf16x2(acc[j][half * 2] * mv,
                                          acc[j][half * 2 + 1] * mv);
    }
}

// ============ kernel 3: post layers, mu2, mu, pooled partials (1 m-tile/warp) ============
__global__ void __launch_bounds__(128) post_kernel(
    const float* __restrict__ xv, const int* __restrict__ mask,
    const float* __restrict__ mu1,
    const float* __restrict__ postb, const float* __restrict__ mu2b)
{
    __shared__ uint32_t sW[3 * 2304];    // layers 2,3,4
    __shared__ float sP[4][64];
    int b  = blockIdx.x >> 6;
    int n0 = (blockIdx.x & 63) << 6;
    int tid = threadIdx.x, wid = tid >> 5, lane = tid & 31;
    int lr = lane >> 2, lc = lane & 3;
    int row0 = n0 + wid * 16 + lr;

    for (int i = tid; i < 3 * 2304 / 4; i += 128)
        ((uint4*)sW)[i] = ((const uint4*)(d_wT + 2 * 2304))[i];

    uint32_t w[8][2];
    {
        const uint32_t* s0 = d_mu_pool_b16 + (size_t)(b * N_ + row0) * 32;
#pragma unroll
        for (int j = 0; j < 8; j++) {
            w[j][0] = s0[j * 4 + lc];  w[j][1] = s0[8 * 32 + j * 4 + lc];
        }
    }
    __syncthreads();
    float acc[8][4];
    init_bias(acc, postb, lc);      layer_mma(acc, w, sW,            lr, lc); pack_words(acc, w, true);
    init_bias(acc, postb + 64, lc); layer_mma(acc, w, sW + 2304,     lr, lc); pack_words(acc, w, true);
    init_bias(acc, mu2b, lc);       layer_mma(acc, w, sW + 2 * 2304, lr, lc);   // mu2, no relu

    float x0 = xv[b * N_ + row0],      x8  = xv[b * N_ + row0 + 8];
    float m0v = (float)mask[b * N_ + row0],  m8v  = (float)mask[b * N_ + row0 + 8];
    uint32_t* d0 = d_mu_b16 + (size_t)(b * N_ + row0) * 32;

    float ps[8][2];
#pragma unroll
    for (int j = 0; j < 8; j++) {
        int c0 = j * 8 + 2 * lc;
        float u0 = mu1[c0], u1 = mu1[c0 + 1];
        float v00 = fmaxf(fmaxf(x0 * u0, 0.f) * m0v + acc[j][0] * m0v, 0.f);
        float v01 = fmaxf(fmaxf(x0 * u1, 0.f) * m0v + acc[j][1] * m0v, 0.f);
        float v80 = fmaxf(fmaxf(x8 * u0, 0.f) * m8v + acc[j][2] * m8v, 0.f);
        float v81 = fmaxf(fmaxf(x8 * u1, 0.f) * m8v + acc[j][3] * m8v, 0.f);
        d0[j * 4 + lc]          = pack_bf16x2(v00, v01);
        d0[8 * 32 + j * 4 + lc] = pack_bf16x2(v80, v81);
        ps[j][0] = x0 * v00 + x8 * v80;
        ps[j][1] = x0 * v01 + x8 * v81;
    }
#pragma unroll
    for (int j = 0; j < 8; j++) {
#pragma unroll
        for (int h = 0; h < 2; h++) {
            float t = ps[j][h];
            t += __shfl_xor_sync(0xffffffffu, t, 4);
            t += __shfl_xor_sync(0xffffffffu, t, 8);
            t += __shfl_xor_sync(0xffffffffu, t, 16);
            if (lr == 0) sP[wid][j * 8 + 2 * lc + h] = t;
        }
    }
    __syncthreads();
    if (tid < 64)
        d_partial[(b * 64 + (blockIdx.x & 63)) * 64 + tid] =
            sP[0][tid] + sP[1][tid] + sP[2][tid] + sP[3][tid];
}

// ============ kernel 4: q head, 1 m-tile/warp (includes pooled->q1->c1 fold) ============
__global__ void __launch_bounds__(128) q_kernel(
    const int* __restrict__ mask,
    const float* __restrict__ q1W, const float* __restrict__ q1b,
    const float* __restrict__ qregW, const float* __restrict__ qregb,
    const float* __restrict__ q2b,
    const float* __restrict__ qW, const float* __restrict__ qb,
    float* __restrict__ out)
{
    __shared__ uint32_t sW[2304 + 1152];   // q2 layer + qreg lower half
    __shared__ float pooled[64], q1s[64], c1s[32];
    __shared__ float red[2][64];
    int b  = blockIdx.x >> 6;
    int n0 = (blockIdx.x & 63) << 6;
    int tid = threadIdx.x, wid = tid >> 5, lane = tid & 31;
    int lr = lane >> 2, lc = lane & 3;

    for (int i = tid; i < (2304 + 1152) / 4; i += 128)
        ((uint4*)sW)[i] = (i < 2304 / 4) ? ((const uint4*)(d_wT + 5 * 2304))[i]
                                         : ((const uint4*)d_wTq)[i - 2304 / 4];

    {   // pooled reduce: 2 groups over t, coalesced in d
        int d = tid & 63, g = tid >> 6;
        float s = 0.f;
#pragma unroll 4
        for (int t = g; t < 64; t += 2) s += d_partial[(b * 64 + t) * 64 + d];
        red[g][d] = s;
    }
    __syncthreads();
    if (tid < 64) pooled[tid] = red[0][tid] + red[1][tid];
    __syncthreads();
    if (tid < 64) {
        float a = q1b[tid];
#pragma unroll 8
        for (int k = 0; k < 64; k++) a = fmaf(pooled[k], q1W[k * 64 + tid], a);
        q1s[tid] = a;
    }
    __syncthreads();
    if (tid < 32) {
        float c = qregb[tid];
#pragma unroll 8
        for (int k = 0; k < 64; k++) c = fmaf(q1s[k], qregW[k * 32 + tid], c);
        c1s[tid] = c;
    }
    __syncthreads();

    int row0 = n0 + wid * 16 + lr;
    uint32_t w[8][2];
    {
        const uint32_t* s0 = d_mu_b16 + (size_t)(b * N_ + row0) * 32;
#pragma unroll
        for (int j = 0; j < 8; j++) {
            w[j][0] = s0[j * 4 + lc];  w[j][1] = s0[8 * 32 + j * 4 + lc];
        }
    }
    float acc[8][4];
    init_bias(acc, q2b, lc);
    layer_mma(acc, w, sW, lr, lc);          // q2 (no relu)
    pack_words(acc, w, false);

    // qreg mma: N=32, acc init = c1
    float qa[4][4];
#pragma unroll
    for (int j = 0; j < 4; j++) {
        int c0 = j * 8 + 2 * lc;
        qa[j][0] = qa[j][2] = c1s[c0];
        qa[j][1] = qa[j][3] = c1s[c0 + 1];
    }
    const uint32_t* sQ = sW + 2304;
#pragma unroll
    for (int kt = 0; kt < 4; kt++) {
        uint32_t x0[4] = { w[2 * kt][0], w[2 * kt][1], w[2 * kt + 1][0], w[2 * kt + 1][1] };
#pragma unroll
        for (int j = 0; j < 4; j++) {
            uint32_t bb[2];
            bb[0] = sQ[(j * 8 + lr) * 36 + kt * 8 + lc];
            bb[1] = sQ[(j * 8 + lr) * 36 + kt * 8 + lc + 4];
            mma_bf16(qa[j], x0, bb);
        }
    }
    float s00 = 0.f, s08 = 0.f;
#pragma unroll
    for (int j = 0; j < 4; j++) {
        int c0 = j * 8 + 2 * lc;
        float wq0 = qW[c0], wq1 = qW[c0 + 1];
        s00 += fmaxf(qa[j][0], 0.f) * wq0 + fmaxf(qa[j][1], 0.f) * wq1;
        s08 += fmaxf(qa[j][2], 0.f) * wq0 + fmaxf(qa[j][3], 0.f) * wq1;
    }
#pragma unroll
    for (int d = 1; d <= 2; d <<= 1) {
        s00 += __shfl_xor_sync(0xffffffffu, s00, d);
        s08 += __shfl_xor_sync(0xffffffffu, s08, d);
    }
    if (lc == 0) {
        float q0 = s00 + qb[0], q8 = s08 + qb[0];
        if (mask[b * N_ + row0] == 0)      q0  = -99999.0f;
        if (mask[b * N_ + row0 + 8] == 0)  q8  = -99999.0f;
        out[b * N_ + row0]      = q0;
        out[b * N_ + row0 + 8]  = q8;
    }
}

// ================= launcher =================
extern "C" void kernel_launch(void* const* d_in, const int* in_sizes, int n_in,
                              void* d_out, int out_size) {
    const float* xv    = (const float*)d_in[0];
    const float* adj   = (const float*)d_in[2];   // edges_weight_adj (d_in[1] is the dead 'adj')
    const int*   mask  = (const int*)  d_in[3];
    const float* mu1   = (const float*)d_in[4];
    const float* mu2W  = (const float*)d_in[5];
    const float* mu2b  = (const float*)d_in[6];
    const float* preW  = (const float*)d_in[7];
    const float* preb  = (const float*)d_in[8];
    const float* postW = (const float*)d_in[9];
    const float* postb = (const float*)d_in[10];
    const float* q1W   = (const float*)d_in[11];
    const float* q1b   = (const float*)d_in[12];
    const float* q2W   = (const float*)d_in[13];
    const float* q2b   = (const float*)d_in[14];
    const float* qregW = (const float*)d_in[15];
    const float* qregb = (const float*)d_in[16];
    const float* qW    = (const float*)d_in[17];
    const float* qb    = (const float*)d_in[18];
    float* out = (float*)d_out;

    cudaFuncSetAttribute(gemm_kernel, cudaFuncAttributeMaxDynamicSharedMemorySize, GEMM_SMEM);

    wprep_kernel<<<64, 256>>>(preW, postW, mu2W, q2W, qregW);
    prep_kernel<<<512, 128>>>(xv, mask, mu1, preb);
    gemm_kernel<<<256, 256, GEMM_SMEM>>>(adj, mask);
    post_kernel<<<512, 128>>>(xv, mask, mu1, postb, mu2b);
    q_kernel<<<512, 128>>>(mask, q1W, q1b, qregW, qregb, q2b, qW, qb, out);
}

// round 16
// speedup vs baseline: 1.2273x; 1.2273x over previous
#include <cuda_runtime.h>
#include <cuda_bf16.h>
#include <cstdint>

#define DEVINL __device__ __forceinline__

constexpr int B_ = 8;
constexpr int N_ = 4096;

// ---------------- device scratch (no allocations allowed) ----------------
__device__ uint32_t d_Bfrag[(size_t)B_ * 131072];        // fragment-major mu_pre (GEMM B operand)
__device__ uint32_t d_mu_b16[(size_t)B_ * N_ * 32];      // final mu, bf16x2 dim-pairs
__device__ float    d_partial[B_ * 32 * 64];             // per-128-node-block pooled partials
__device__ uint32_t d_wT[6 * 2304];                      // 6 layers W^T bf16, padded stride 36
__device__ uint32_t d_wTq[1152];                         // qregW lower half W^T, stride 36

// ---------------- helpers ----------------
DEVINL uint32_t smem_u32(const void* p) {
    uint32_t a;
    asm("{ .reg .u64 t; cvta.to.shared.u64 t, %1; cvt.u32.u64 %0, t; }" : "=r"(a) : "l"(p));
    return a;
}
DEVINL void cp_async16(uint32_t dst, const void* src) {
    asm volatile("cp.async.cg.shared.global [%0], [%1], 16;\n" :: "r"(dst), "l"(src));
}
DEVINL void cp_commit() { asm volatile("cp.async.commit_group;\n" ::); }
#define CP_WAIT(n) asm volatile("cp.async.wait_group %0;\n" :: "n"(n))

DEVINL uint32_t pack_bf16x2(float lo, float hi) {
    __nv_bfloat162 v = __floats2bfloat162_rn(lo, hi);
    return *(uint32_t*)&v;
}

// mma.sync m16n8k16 bf16 (A row-major, B col-major), fp32 accumulate.
DEVINL void mma_bf16(float* d, const uint32_t* a, const uint32_t* b) {
    asm volatile(
        "mma.sync.aligned.m16n8k16.row.col.f32.bf16.bf16.f32 "
        "{%0,%1,%2,%3}, {%4,%5,%6,%7}, {%8,%9}, {%0,%1,%2,%3};"
        : "+f"(d[0]), "+f"(d[1]), "+f"(d[2]), "+f"(d[3])
        : "r"(a[0]), "r"(a[1]), "r"(a[2]), "r"(a[3]), "r"(b[0]), "r"(b[1]));
}

// ---------------- register-resident 64-wide layer primitives ----------------
// w[j][0] = rows lr, cols j*8+2lc..+1 (bf16x2); w[j][1] = rows lr+8.
// Weight tables use stride 36 words: (j*8+lr)*36 + kt*8+lc.

DEVINL void init_bias(float acc[8][4], const float* __restrict__ bias, int lc) {
#pragma unroll
    for (int j = 0; j < 8; j++) {
        float b0 = bias[j * 8 + 2 * lc], b1 = bias[j * 8 + 2 * lc + 1];
        acc[j][0] = b0; acc[j][1] = b1; acc[j][2] = b0; acc[j][3] = b1;
    }
}
DEVINL void pack_words(const float acc[8][4], uint32_t w[8][2], bool relu) {
#pragma unroll
    for (int j = 0; j < 8; j++) {
        float a0 = acc[j][0], a1 = acc[j][1], a2 = acc[j][2], a3 = acc[j][3];
        if (relu) { a0 = fmaxf(a0, 0.f); a1 = fmaxf(a1, 0.f); a2 = fmaxf(a2, 0.f); a3 = fmaxf(a3, 0.f); }
        w[j][0] = pack_bf16x2(a0, a1);
        w[j][1] = pack_bf16x2(a2, a3);
    }
}
DEVINL void layer_mma(float acc[8][4], const uint32_t w[8][2],
                      const uint32_t* __restrict__ wT, int lr, int lc) {
#pragma unroll
    for (int kt = 0; kt < 4; kt++) {
        uint32_t a[4] = { w[2 * kt][0], w[2 * kt][1], w[2 * kt + 1][0], w[2 * kt + 1][1] };
#pragma unroll
        for (int j = 0; j < 8; j++) {
            uint32_t bb[2];
            bb[0] = wT[(j * 8 + lr) * 36 + kt * 8 + lc];
            bb[1] = wT[(j * 8 + lr) * 36 + kt * 8 + lc + 4];
            mma_bf16(acc[j], a, bb);
        }
    }
}

// ============ kernel 0: convert all layer weights to bf16 W^T (stride 36) ============
__global__ void wprep_kernel(
    const float* __restrict__ preW, const float* __restrict__ postW,
    const float* __restrict__ mu2W, const float* __restrict__ q2W,
    const float* __restrict__ qregW)
{
    int gid = blockIdx.x * 256 + threadIdx.x;
    int gstride = gridDim.x * 256;
    for (int idx = gid; idx < 6 * 2304; idx += gstride) {
        int l = idx / 2304, r = idx % 2304, dout = r / 36, col = r % 36;
        uint32_t v = 0;
        if (col < 32) {
            const float* W;
            switch (l) {
                case 0: W = preW;         break;
                case 1: W = preW + 4096;  break;
                case 2: W = postW;        break;
                case 3: W = postW + 4096; break;
                case 4: W = mu2W;         break;
                default: W = q2W;         break;
            }
            v = pack_bf16x2(W[(2 * col) * 64 + dout], W[(2 * col + 1) * 64 + dout]);
        }
        d_wT[idx] = v;
    }
    for (int idx = gid; idx < 1152; idx += gstride) {
        int rh = idx / 36, col = idx % 36;
        uint32_t v = 0;
        if (col < 32)
            v = pack_bf16x2(qregW[(64 + 2 * col) * 32 + rh],
                            qregW[(64 + 2 * col + 1) * 32 + rh]);
        d_wTq[idx] = v;
    }
}

// ============ kernel 1: mu0 -> 2 pre layers -> fragment-major d_Bfrag ============
// LAYOUT A (proven 157.7): per chunk c: [kt][j][slot][h] -> uint2 per (kt,j) in gemm
__global__ void __launch_bounds__(128) prep_kernel(
    const float* __restrict__ xv, const int* __restrict__ mask,
    const float* __restrict__ mu1, const float* __restrict__ preb)
{
    __shared__ uint32_t sS[64 * 36];        // [node][kword] staging, stride 36
    __shared__ uint32_t sW[2 * 2304];       // layers 0,1 weights
    int b  = blockIdx.x >> 6;
    int n0 = (blockIdx.x & 63) << 6;
    int tid = threadIdx.x, wid = tid >> 5, lane = tid & 31;
    int lr = lane >> 2, lc = lane & 3;
    int rl0 = wid * 16 + lr;
    int row0 = n0 + rl0;

    for (int i = tid; i < 2 * 2304 / 4; i += 128)
        ((uint4*)sW)[i] = ((const uint4*)d_wT)[i];

    float xv0 = xv[b * N_ + row0],     xv8 = xv[b * N_ + row0 + 8];
    float mv0 = (float)mask[b * N_ + row0], mv8 = (float)mask[b * N_ + row0 + 8];

    uint32_t w[8][2];
#pragma unroll
    for (int j = 0; j < 8; j++) {
        int c0 = j * 8 + 2 * lc;
        float u0 = mu1[c0], u1 = mu1[c0 + 1];
        w[j][0] = pack_bf16x2(fmaxf(xv0 * u0, 0.f) * mv0, fmaxf(xv0 * u1, 0.f) * mv0);
        w[j][1] = pack_bf16x2(fmaxf(xv8 * u0, 0.f) * mv8, fmaxf(xv8 * u1, 0.f) * mv8);
    }
    __syncthreads();
    float acc[8][4];
    init_bias(acc, preb, lc);       layer_mma(acc, w, sW,        lr, lc); pack_words(acc, w, true);
    init_bias(acc, preb + 64, lc);  layer_mma(acc, w, sW + 2304, lr, lc); pack_words(acc, w, true);

#pragma unroll
    for (int j = 0; j < 8; j++) {
        sS[rl0 * 36 + j * 4 + lc]       = w[j][0];
        sS[(rl0 + 8) * 36 + j * 4 + lc] = w[j][1];
    }
    __syncthreads();

    // scatter to fragment-major layout A; warp handles j = 2*wid, 2*wid+1
    int lrw = lane & 7, lcw = lane >> 3;
    int slot = lcw * 8 + lrw;
    int c0 = n0 >> 5;                     // first chunk covered by this block
#pragma unroll
    for (int cl = 0; cl < 2; cl++)
#pragma unroll
        for (int kt = 0; kt < 2; kt++)
#pragma unroll
            for (int h = 0; h < 2; h++)
#pragma unroll
                for (int jj = 0; jj < 2; jj++) {
                    int j  = wid * 2 + jj;
                    int dd = j * 8 + lrw;
                    int jp = cl * 16 + kt * 8 + lcw + 4 * h;   // local node-pair
                    uint32_t w0 = sS[(2 * jp) * 36 + (dd >> 1)];
                    uint32_t w1 = sS[(2 * jp + 1) * 36 + (dd >> 1)];
                    uint32_t out = __byte_perm(w0, w1, (dd & 1) ? 0x7632 : 0x5410);
                    d_Bfrag[(size_t)b * 131072 + (size_t)(c0 + cl) * 1024 +
                            kt * 512 + j * 64 + slot * 2 + h] = out;
                }
}

// ============ kernel 2: warp-decoupled GEMM (157.7 mainloop) + fused post ============
// 8 warps/CTA, 16 rows/warp, private pad-40 4-stage rings; B via uint2 per (kt,j).
// Epilogue fuses mask -> post0 -> post1 -> mu2 -> mu (+ pooled partials).
constexpr int A_STRIDE = 40;                          // words per row (160B)
constexpr int WSTAGE_WORDS = 16 * A_STRIDE;           // 640 words = 2560B per warp-stage
constexpr int RING_WORDS   = 8 * 4 * WSTAGE_WORDS;    // 20480
constexpr int WT_WORDS     = 3 * 2304;                // 6912
constexpr int GEMM_SMEM    = (RING_WORDS + WT_WORDS + 8 * 64) * 4;  // 111616 B

__global__ void __launch_bounds__(256, 2) gemm_kernel(
    const float* __restrict__ adj, const int* __restrict__ mask,
    const float* __restrict__ xv, const float* __restrict__ mu1,
    const float* __restrict__ postb, const float* __restrict__ mu2b)
{
    extern __shared__ __align__(16) float smemf[];
    const uint32_t sm_base = smem_u32(smemf);
    int tid = threadIdx.x, wid = tid >> 5, lane = tid & 31;
    int b  = blockIdx.x >> 5;
    int m0 = (blockIdx.x & 31) << 7;
    const int wrow = wid * 16;
    const float* adjb = adj + (size_t)b * N_ * N_ + (size_t)(m0 + wrow) * N_;
    const uint32_t* bfb = d_Bfrag + (size_t)b * 131072;

    const uint32_t warpbase = sm_base + (uint32_t)(wid * 4 * WSTAGE_WORDS) * 4u;
    float* const warpf = smemf + wid * 4 * WSTAGE_WORDS;
    uint32_t* const sWt = (uint32_t*)(smemf + RING_WORDS);
    float* const sPf = smemf + RING_WORDS + WT_WORDS;

    auto load_stage = [&](int slot, int chunk) {
        uint32_t base = warpbase + (uint32_t)(slot * WSTAGE_WORDS) * 4u;
        int kb = chunk * 32;
#pragma unroll
        for (int i = 0; i < 4; i++) {
            int idx = lane + i * 32;
            int row = idx >> 3, seg = idx & 7;
            cp_async16(base + (uint32_t)(row * A_STRIDE * 4 + seg * 16),
                       adjb + (size_t)row * N_ + kb + seg * 4);
        }
    };

    load_stage(0, 0); cp_commit();
    load_stage(1, 1); cp_commit();
    load_stage(2, 2); cp_commit();

    // stage post-layer weights into smem (used only in epilogue)
    for (int i = tid; i < WT_WORDS / 4; i += 256)
        ((uint4*)sWt)[i] = ((const uint4*)(d_wT + 2 * 2304))[i];

    float acc[8][4];
#pragma unroll
    for (int j = 0; j < 8; j++)
#pragma unroll
        for (int r = 0; r < 4; r++) acc[j][r] = 0.0f;

    const int lr = lane >> 2, lc = lane & 3;
    const int bslot = lc * 8 + lr;        // word-pair slot within a fragment line

    for (int c = 0; c < 128; c++) {
        CP_WAIT(2);                       // this warp's chunk-c group done
        __syncwarp();                     // cross-lane visibility within warp
        if (c + 3 < 128) load_stage((c + 3) & 3, c + 3);
        cp_commit();

        const float* sA = warpf + (c & 3) * WSTAGE_WORDS;
        const uint32_t* bc = bfb + (size_t)c * 1024;
#pragma unroll
        for (int kt = 0; kt < 2; kt++) {
            int k0 = kt * 16;
            uint32_t af[4];
            {
                float2 p0 = *(const float2*)&sA[(lr    ) * A_STRIDE + k0 + 2 * lc    ];
                float2 p1 = *(const float2*)&sA[(lr + 8) * A_STRIDE + k0 + 2 * lc    ];
                float2 p2 = *(const float2*)&sA[(lr    ) * A_STRIDE + k0 + 2 * lc + 8];
                float2 p3 = *(const float2*)&sA[(lr + 8) * A_STRIDE + k0 + 2 * lc + 8];
                af[0] = pack_bf16x2(p0.x, p0.y);
                af[1] = pack_bf16x2(p1.x, p1.y);
                af[2] = pack_bf16x2(p2.x, p2.y);
                af[3] = pack_bf16x2(p3.x, p3.y);
            }
            const uint32_t* bk = bc + kt * 512;
#pragma unroll
            for (int j = 0; j < 8; j++) {
                uint2 bv = *(const uint2*)&bk[j * 64 + bslot * 2];
                uint32_t bb[2] = { bv.x, bv.y };
                mma_bf16(acc[j], af, bb);
            }
        }
    }

    // ---- fused epilogue: mask -> post layers -> mu2 -> mu -> pooled partials ----
    CP_WAIT(0);
    __syncthreads();                      // weights + all ring traffic settled

    int row0 = m0 + wrow + lr;
    float mv0 = (float)mask[b * N_ + row0], mv8 = (float)mask[b * N_ + row0 + 8];
    uint32_t w[8][2];
#pragma unroll
    for (int j = 0; j < 8; j++) {
        w[j][0] = pack_bf16x2(acc[j][0] * mv0, acc[j][1] * mv0);
        w[j][1] = pack_bf16x2(acc[j][2] * mv8, acc[j][3] * mv8);
    }
    float a2[8][4];
    init_bias(a2, postb, lc);      layer_mma(a2, w, sWt,        lr, lc); pack_words(a2, w, true);
    init_bias(a2, postb + 64, lc); layer_mma(a2, w, sWt + 2304, lr, lc); pack_words(a2, w, true);
    init_bias(a2, mu2b, lc);       layer_mma(a2, w, sWt + 4608, lr, lc);   // mu2, no relu

    float x0 = xv[b * N_ + row0], x8 = xv[b * N_ + row0 + 8];
    uint32_t* d0 = d_mu_b16 + (size_t)(b * N_ + row0) * 32;

    float ps[8][2];
#pragma unroll
    for (int j = 0; j < 8; j++) {
        int c0 = j * 8 + 2 * lc;
        float u0 = mu1[c0], u1 = mu1[c0 + 1];
        float v00 = fmaxf(fmaxf(x0 * u0, 0.f) * mv0 + a2[j][0] * mv0, 0.f);
        float v01 = fmaxf(fmaxf(x0 * u1, 0.f) * mv0 + a2[j][1] * mv0, 0.f);
        float v80 = fmaxf(fmaxf(x8 * u0, 0.f) * mv8 + a2[j][2] * mv8, 0.f);
        float v81 = fmaxf(fmaxf(x8 * u1, 0.f) * mv8 + a2[j][3] * mv8, 0.f);
        d0[j * 4 + lc]          = pack_bf16x2(v00, v01);
        d0[8 * 32 + j * 4 + lc] = pack_bf16x2(v80, v81);
        ps[j][0] = x0 * v00 + x8 * v80;
        ps[j][1] = x0 * v01 + x8 * v81;
    }
#pragma unroll
    for (int j = 0; j < 8; j++) {
#pragma unroll
        for (int h = 0; h < 2; h++) {
            float t = ps[j][h];
            t += __shfl_xor_sync(0xffffffffu, t, 4);
            t += __shfl_xor_sync(0xffffffffu, t, 8);
            t += __shfl_xor_sync(0xffffffffu, t, 16);
            if (lr == 0) sPf[wid * 64 + j * 8 + 2 * lc + h] = t;
        }
    }
    __syncthreads();
    if (tid < 64) {
        float s = 0.f;
#pragma unroll
        for (int ww = 0; ww < 8; ww++) s += sPf[ww * 64 + tid];
        d_partial[(b * 32 + (blockIdx.x & 31)) * 64 + tid] = s;
    }
}

// ============ kernel 3: q head, 1 m-tile/warp (includes pooled->q1->c1 fold) ============
__global__ void __launch_bounds__(128) q_kernel(
    const int* __restrict__ mask,
    const float* __restrict__ q1W, const float* __restrict__ q1b,
    const float* __restrict__ qregW, const float* __restrict__ qregb,
    const float* __restrict__ q2b,
    const float* __restrict__ qW, const float* __restrict__ qb,
    float* __restrict__ out)
{
    __shared__ uint32_t sW[2304 + 1152];   // q2 layer + qreg lower half
    __shared__ float pooled[64], q1s[64], c1s[32];
    __shared__ float red[2][64];
    int b  = blockIdx.x >> 6;
    int n0 = (blockIdx.x & 63) << 6;
    int tid = threadIdx.x, wid = tid >> 5, lane = tid & 31;
    int lr = lane >> 2, lc = lane & 3;

    for (int i = tid; i < (2304 + 1152) / 4; i += 128)
        ((uint4*)sW)[i] = (i < 2304 / 4) ? ((const uint4*)(d_wT + 5 * 2304))[i]
                                         : ((const uint4*)d_wTq)[i - 2304 / 4];

    {   // pooled reduce: 2 groups over t, coalesced in d
        int d = tid & 63, g = tid >> 6;
        float s = 0.f;
#pragma unroll 4
        for (int t = g; t < 32; t += 2) s += d_partial[(b * 32 + t) * 64 + d];
        red[g][d] = s;
    }
    __syncthreads();
    if (tid < 64) pooled[tid] = red[0][tid] + red[1][tid];
    __syncthreads();
    if (tid < 64) {
        float a = q1b[tid];
#pragma unroll 8
        for (int k = 0; k < 64; k++) a = fmaf(pooled[k], q1W[k * 64 + tid], a);
        q1s[tid] = a;
    }
    __syncthreads();
    if (tid < 32) {
        float c = qregb[tid];
#pragma unroll 8
        for (int k = 0; k < 64; k++) c = fmaf(q1s[k], qregW[k * 32 + tid], c);
        c1s[tid] = c;
    }
    __syncthreads();

    int row0 = n0 + wid * 16 + lr;
    uint32_t w[8][2];
    {
        const uint32_t* s0 = d_mu_b16 + (size_t)(b * N_ + row0) * 32;
#pragma unroll
        for (int j = 0; j < 8; j++) {
            w[j][0] = s0[j * 4 + lc];  w[j][1] = s0[8 * 32 + j * 4 + lc];
        }
    }
    float acc[8][4];
    init_bias(acc, q2b, lc);
    layer_mma(acc, w, sW, lr, lc);          // q2 (no relu)
    pack_words(acc, w, false);

    // qreg mma: N=32, acc init = c1
    float qa[4][4];
#pragma unroll
    for (int j = 0; j < 4; j++) {
        int c0 = j * 8 + 2 * lc;
        qa[j][0] = qa[j][2] = c1s[c0];
        qa[j][1] = qa[j][3] = c1s[c0 + 1];
    }
    const uint32_t* sQ = sW + 2304;
#pragma unroll
    for (int kt = 0; kt < 4; kt++) {
        uint32_t x0[4] = { w[2 * kt][0], w[2 * kt][1], w[2 * kt + 1][0], w[2 * kt + 1][1] };
#pragma unroll
        for (int j = 0; j < 4; j++) {
            uint32_t bb[2];
            bb[0] = sQ[(j * 8 + lr) * 36 + kt * 8 + lc];
            bb[1] = sQ[(j * 8 + lr) * 36 + kt * 8 + lc + 4];
            mma_bf16(qa[j], x0, bb);
        }
    }
    float s00 = 0.f, s08 = 0.f;
#pragma unroll
    for (int j = 0; j < 4; j++) {
        int c0 = j * 8 + 2 * lc;
        float wq0 = qW[c0], wq1 = qW[c0 + 1];
        s00 += fmaxf(qa[j][0], 0.f) * wq0 + fmaxf(qa[j][1], 0.f) * wq1;
        s08 += fmaxf(qa[j][2], 0.f) * wq0 + fmaxf(qa[j][3], 0.f) * wq1;
    }
#pragma unroll
    for (int d = 1; d <= 2; d <<= 1) {
        s00 += __shfl_xor_sync(0xffffffffu, s00, d);
        s08 += __shfl_xor_sync(0xffffffffu, s08, d);
    }
    if (lc == 0) {
        float q0 = s00 + qb[0], q8 = s08 + qb[0];
        if (mask[b * N_ + row0] == 0)      q0  = -99999.0f;
        if (mask[b * N_ + row0 + 8] == 0)  q8  = -99999.0f;
        out[b * N_ + row0]      = q0;
        out[b * N_ + row0 + 8]  = q8;
    }
}

// ================= launcher =================
extern "C" void kernel_launch(void* const* d_in, const int* in_sizes, int n_in,
                              void* d_out, int out_size) {
    const float* xv    = (const float*)d_in[0];
    const float* adj   = (const float*)d_in[2];   // edges_weight_adj (d_in[1] is the dead 'adj')
    const int*   mask  = (const int*)  d_in[3];
    const float* mu1   = (const float*)d_in[4];
    const float* mu2W  = (const float*)d_in[5];
    const float* mu2b  = (const float*)d_in[6];
    const float* preW  = (const float*)d_in[7];
    const float* preb  = (const float*)d_in[8];
    const float* postW = (const float*)d_in[9];
    const float* postb = (const float*)d_in[10];
    const float* q1W   = (const float*)d_in[11];
    const float* q1b   = (const float*)d_in[12];
    const float* q2W   = (const float*)d_in[13];
    const float* q2b   = (const float*)d_in[14];
    const float* qregW = (const float*)d_in[15];
    const float* qregb = (const float*)d_in[16];
    const float* qW    = (const float*)d_in[17];
    const float* qb    = (const float*)d_in[18];
    float* out = (float*)d_out;

    cudaFuncSetAttribute(gemm_kernel, cudaFuncAttributeMaxDynamicSharedMemorySize, GEMM_SMEM);

    wprep_kernel<<<64, 256>>>(preW, postW, mu2W, q2W, qregW);
    prep_kernel<<<512, 128>>>(xv, mask, mu1, preb);
    gemm_kernel<<<256, 256, GEMM_SMEM>>>(adj, mask, xv, mu1, postb, mu2b);
    q_kernel<<<512, 128>>>(mask, q1W, q1b, qregW, qregb, q2b, qW, qb, out);
}

// round 17
// speedup vs baseline: 1.4056x; 1.1453x over previous
#include <cuda_runtime.h>
#include <cuda_bf16.h>
#include <cstdint>

#define DEVINL __device__ __forceinline__

constexpr int B_ = 8;
constexpr int N_ = 4096;

// ---------------- device scratch (no allocations allowed) ----------------
__device__ uint32_t d_Bfrag[(size_t)B_ * 131072];        // fragment-major mu_pre (GEMM B operand)
__device__ uint32_t d_mu_pool_b16[(size_t)B_ * N_ * 32]; // [B][N][32 kwords] bf16x2 dim-pairs
__device__ uint32_t d_mu_b16[(size_t)B_ * N_ * 32];      // final mu, bf16x2 dim-pairs
__device__ float    d_partial[B_ * 64 * 64];             // per-64-node-block pooled partials
__device__ uint32_t d_wT[6 * 2304];                      // 6 layers W^T bf16, padded stride 36
__device__ uint32_t d_wTq[1152];                         // qregW lower half W^T, stride 36

// ---------------- helpers ----------------
DEVINL uint32_t smem_u32(const void* p) {
    uint32_t a;
    asm("{ .reg .u64 t; cvta.to.shared.u64 t, %1; cvt.u32.u64 %0, t; }" : "=r"(a) : "l"(p));
    return a;
}
DEVINL void cp_async16(uint32_t dst, const void* src) {
    asm volatile("cp.async.cg.shared.global [%0], [%1], 16;\n" :: "r"(dst), "l"(src));
}
DEVINL void cp_commit() { asm volatile("cp.async.commit_group;\n" ::); }
#define CP_WAIT(n) asm volatile("cp.async.wait_group %0;\n" :: "n"(n))

DEVINL uint32_t pack_bf16x2(float lo, float hi) {
    __nv_bfloat162 v = __floats2bfloat162_rn(lo, hi);
    return *(uint32_t*)&v;
}

// mma.sync m16n8k16 bf16 (A row-major, B col-major), fp32 accumulate.
DEVINL void mma_bf16(float* d, const uint32_t* a, const uint32_t* b) {
    asm volatile(
        "mma.sync.aligned.m16n8k16.row.col.f32.bf16.bf16.f32 "
        "{%0,%1,%2,%3}, {%4,%5,%6,%7}, {%8,%9}, {%0,%1,%2,%3};"
        : "+f"(d[0]), "+f"(d[1]), "+f"(d[2]), "+f"(d[3])
        : "r"(a[0]), "r"(a[1]), "r"(a[2]), "r"(a[3]), "r"(b[0]), "r"(b[1]));
}

// ---------------- register-resident 64-wide layer primitives ----------------
// w[j][0] = rows lr, cols j*8+2lc..+1 (bf16x2); w[j][1] = rows lr+8.
// Weight tables use stride 36 words: (j*8+lr)*36 + kt*8+lc.

DEVINL void init_bias(float acc[8][4], const float* __restrict__ bias, int lc) {
#pragma unroll
    for (int j = 0; j < 8; j++) {
        float b0 = bias[j * 8 + 2 * lc], b1 = bias[j * 8 + 2 * lc + 1];
        acc[j][0] = b0; acc[j][1] = b1; acc[j][2] = b0; acc[j][3] = b1;
    }
}
DEVINL void pack_words(const float acc[8][4], uint32_t w[8][2], bool relu) {
#pragma unroll
    for (int j = 0; j < 8; j++) {
        float a0 = acc[j][0], a1 = acc[j][1], a2 = acc[j][2], a3 = acc[j][3];
        if (relu) { a0 = fmaxf(a0, 0.f); a1 = fmaxf(a1, 0.f); a2 = fmaxf(a2, 0.f); a3 = fmaxf(a3, 0.f); }
        w[j][0] = pack_bf16x2(a0, a1);
        w[j][1] = pack_bf16x2(a2, a3);
    }
}
DEVINL void layer_mma(float acc[8][4], const uint32_t w[8][2],
                      const uint32_t* __restrict__ wT, int lr, int lc) {
#pragma unroll
    for (int kt = 0; kt < 4; kt++) {
        uint32_t a[4] = { w[2 * kt][0], w[2 * kt][1], w[2 * kt + 1][0], w[2 * kt + 1][1] };
#pragma unroll
        for (int j = 0; j < 8; j++) {
            uint32_t bb[2];
            bb[0] = wT[(j * 8 + lr) * 36 + kt * 8 + lc];
            bb[1] = wT[(j * 8 + lr) * 36 + kt * 8 + lc + 4];
            mma_bf16(acc[j], a, bb);
        }
    }
}
// one 64x64 layer on TWO m-tiles sharing each weight-fragment load
DEVINL void layer_mma2(float a0[8][4], float a1[8][4],
                       const uint32_t w0[8][2], const uint32_t w1[8][2],
                       const uint32_t* __restrict__ wT, int lr, int lc) {
#pragma unroll
    for (int kt = 0; kt < 4; kt++) {
        uint32_t x0[4] = { w0[2 * kt][0], w0[2 * kt][1], w0[2 * kt + 1][0], w0[2 * kt + 1][1] };
        uint32_t x1[4] = { w1[2 * kt][0], w1[2 * kt][1], w1[2 * kt + 1][0], w1[2 * kt + 1][1] };
#pragma unroll
        for (int j = 0; j < 8; j++) {
            uint32_t bb[2];
            bb[0] = wT[(j * 8 + lr) * 36 + kt * 8 + lc];
            bb[1] = wT[(j * 8 + lr) * 36 + kt * 8 + lc + 4];
            mma_bf16(a0[j], x0, bb);
            mma_bf16(a1[j], x1, bb);
        }
    }
}

// ============ kernel 0: convert all layer weights to bf16 W^T (stride 36) ============
__global__ void wprep_kernel(
    const float* __restrict__ preW, const float* __restrict__ postW,
    const float* __restrict__ mu2W, const float* __restrict__ q2W,
    const float* __restrict__ qregW)
{
    int gid = blockIdx.x * 256 + threadIdx.x;
    int gstride = gridDim.x * 256;
    for (int idx = gid; idx < 6 * 2304; idx += gstride) {
        int l = idx / 2304, r = idx % 2304, dout = r / 36, col = r % 36;
        uint32_t v = 0;
        if (col < 32) {
            const float* W;
            switch (l) {
                case 0: W = preW;         break;
                case 1: W = preW + 4096;  break;
                case 2: W = postW;        break;
                case 3: W = postW + 4096; break;
                case 4: W = mu2W;         break;
                default: W = q2W;         break;
            }
            v = pack_bf16x2(W[(2 * col) * 64 + dout], W[(2 * col + 1) * 64 + dout]);
        }
        d_wT[idx] = v;
    }
    for (int idx = gid; idx < 1152; idx += gstride) {
        int rh = idx / 36, col = idx % 36;
        uint32_t v = 0;
        if (col < 32)
            v = pack_bf16x2(qregW[(64 + 2 * col) * 32 + rh],
                            qregW[(64 + 2 * col + 1) * 32 + rh]);
        d_wTq[idx] = v;
    }
}

// ============ kernel 1: mu0 -> 2 pre layers -> fragment-major d_Bfrag ============
// LAYOUT A (proven 157.7): per chunk c: [kt][j][slot][h] -> uint2 per (kt,j) in gemm
__global__ void __launch_bounds__(128) prep_kernel(
    const float* __restrict__ xv, const int* __restrict__ mask,
    const float* __restrict__ mu1, const float* __restrict__ preb)
{
    __shared__ uint32_t sS[64 * 36];        // [node][kword] staging, stride 36
    __shared__ uint32_t sW[2 * 2304];       // layers 0,1 weights
    int b  = blockIdx.x >> 6;
    int n0 = (blockIdx.x & 63) << 6;
    int tid = threadIdx.x, wid = tid >> 5, lane = tid & 31;
    int lr = lane >> 2, lc = lane & 3;
    int rl0 = wid * 16 + lr;
    int row0 = n0 + rl0;

    for (int i = tid; i < 2 * 2304 / 4; i += 128)
        ((uint4*)sW)[i] = ((const uint4*)d_wT)[i];

    float xv0 = xv[b * N_ + row0],     xv8 = xv[b * N_ + row0 + 8];
    float mv0 = (float)mask[b * N_ + row0], mv8 = (float)mask[b * N_ + row0 + 8];

    uint32_t w[8][2];
#pragma unroll
    for (int j = 0; j < 8; j++) {
        int c0 = j * 8 + 2 * lc;
        float u0 = mu1[c0], u1 = mu1[c0 + 1];
        w[j][0] = pack_bf16x2(fmaxf(xv0 * u0, 0.f) * mv0, fmaxf(xv0 * u1, 0.f) * mv0);
        w[j][1] = pack_bf16x2(fmaxf(xv8 * u0, 0.f) * mv8, fmaxf(xv8 * u1, 0.f) * mv8);
    }
    __syncthreads();
    float acc[8][4];
    init_bias(acc, preb, lc);       layer_mma(acc, w, sW,        lr, lc); pack_words(acc, w, true);
    init_bias(acc, preb + 64, lc);  layer_mma(acc, w, sW + 2304, lr, lc); pack_words(acc, w, true);

#pragma unroll
    for (int j = 0; j < 8; j++) {
        sS[rl0 * 36 + j * 4 + lc]       = w[j][0];
        sS[(rl0 + 8) * 36 + j * 4 + lc] = w[j][1];
    }
    __syncthreads();

    // scatter to fragment-major layout A; warp handles j = 2*wid, 2*wid+1
    int lrw = lane & 7, lcw = lane >> 3;
    int slot = lcw * 8 + lrw;
    int c0 = n0 >> 5;                     // first chunk covered by this block
#pragma unroll
    for (int cl = 0; cl < 2; cl++)
#pragma unroll
        for (int kt = 0; kt < 2; kt++)
#pragma unroll
            for (int h = 0; h < 2; h++)
#pragma unroll
                for (int jj = 0; jj < 2; jj++) {
                    int j  = wid * 2 + jj;
                    int dd = j * 8 + lrw;
                    int jp = cl * 16 + kt * 8 + lcw + 4 * h;   // local node-pair
                    uint32_t w0 = sS[(2 * jp) * 36 + (dd >> 1)];
                    uint32_t w1 = sS[(2 * jp + 1) * 36 + (dd >> 1)];
                    uint32_t out = __byte_perm(w0, w1, (dd & 1) ? 0x7632 : 0x5410);
                    d_Bfrag[(size_t)b * 131072 + (size_t)(c0 + cl) * 1024 +
                            kt * 512 + j * 64 + slot * 2 + h] = out;
                }
}

// ============ kernel 2: warp-decoupled bf16 GEMM, 16 warps/SM (157.7 proven) ============
constexpr int A_STRIDE = 40;                        // words per row (160B)
constexpr int WSTAGE_WORDS = 16 * A_STRIDE;         // 640 words = 2560B per warp-stage
constexpr int GEMM_SMEM = 8 * 4 * WSTAGE_WORDS * 4; // 8 warps x 4 stages = 81920B

__global__ void __launch_bounds__(256, 2) gemm_kernel(
    const float* __restrict__ adj, const int* __restrict__ mask)
{
    extern __shared__ __align__(16) float smemf[];
    const uint32_t sm_base = smem_u32(smemf);
    int tid = threadIdx.x, wid = tid >> 5, lane = tid & 31;
    int b  = blockIdx.x >> 5;
    int m0 = (blockIdx.x & 31) << 7;
    const int wrow = wid * 16;
    const float* adjb = adj + (size_t)b * N_ * N_ + (size_t)(m0 + wrow) * N_;
    const uint32_t* bfb = d_Bfrag + (size_t)b * 131072;

    const uint32_t warpbase = sm_base + (uint32_t)(wid * 4 * WSTAGE_WORDS) * 4u;
    float* const warpf = smemf + wid * 4 * WSTAGE_WORDS;

    auto load_stage = [&](int slot, int chunk) {
        uint32_t base = warpbase + (uint32_t)(slot * WSTAGE_WORDS) * 4u;
        int kb = chunk * 32;
#pragma unroll
        for (int i = 0; i < 4; i++) {
            int idx = lane + i * 32;
            int row = idx >> 3, seg = idx & 7;
            cp_async16(base + (uint32_t)(row * A_STRIDE * 4 + seg * 16),
                       adjb + (size_t)row * N_ + kb + seg * 4);
        }
    };

    load_stage(0, 0); cp_commit();
    load_stage(1, 1); cp_commit();
    load_stage(2, 2); cp_commit();

    float acc[8][4];
#pragma unroll
    for (int j = 0; j < 8; j++)
#pragma unroll
        for (int r = 0; r < 4; r++) acc[j][r] = 0.0f;

    const int lr = lane >> 2, lc = lane & 3;
    const int bslot = lc * 8 + lr;        // word-pair slot within a fragment line

    for (int c = 0; c < 128; c++) {
        CP_WAIT(2);                       // this warp's chunk-c group done
        __syncwarp();                     // cross-lane visibility within warp
        if (c + 3 < 128) load_stage((c + 3) & 3, c + 3);
        cp_commit();

        const float* sA = warpf + (c & 3) * WSTAGE_WORDS;
        const uint32_t* bc = bfb + (size_t)c * 1024;
#pragma unroll
        for (int kt = 0; kt < 2; kt++) {
            int k0 = kt * 16;
            uint32_t af[4];
            {
                float2 p0 = *(const float2*)&sA[(lr    ) * A_STRIDE + k0 + 2 * lc    ];
                float2 p1 = *(const float2*)&sA[(lr + 8) * A_STRIDE + k0 + 2 * lc    ];
                float2 p2 = *(const float2*)&sA[(lr    ) * A_STRIDE + k0 + 2 * lc + 8];
                float2 p3 = *(const float2*)&sA[(lr + 8) * A_STRIDE + k0 + 2 * lc + 8];
                af[0] = pack_bf16x2(p0.x, p0.y);
                af[1] = pack_bf16x2(p1.x, p1.y);
                af[2] = pack_bf16x2(p2.x, p2.y);
                af[3] = pack_bf16x2(p3.x, p3.y);
            }
            const uint32_t* bk = bc + kt * 512;
#pragma unroll
            for (int j = 0; j < 8; j++) {
                uint2 bv = *(const uint2*)&bk[j * 64 + bslot * 2];
                uint32_t bb[2] = { bv.x, bv.y };
                mma_bf16(acc[j], af, bb);
            }
        }
    }

    // epilogue: mask, pack bf16, store kword layout [row][j*4+lc]
#pragma unroll
    for (int half = 0; half < 2; half++) {
        int row = m0 + wrow + lr + half * 8;
        float mv = (float)mask[b * N_ + row];
        uint32_t* dst = d_mu_pool_b16 + (size_t)(b * N_ + row) * 32;
#pragma unroll
        for (int j = 0; j < 8; j++)
            dst[j * 4 + lc] = pack_bf16x2(acc[j][half * 2] * mv,
                                          acc[j][half * 2 + 1] * mv);
    }
}

// ============ kernel 3: post layers, mu2, mu, pooled partials (1 m-tile/warp) ============
__global__ void __launch_bounds__(128) post_kernel(
    const float* __restrict__ xv, const int* __restrict__ mask,
    const float* __restrict__ mu1,
    const float* __restrict__ postb, const float* __restrict__ mu2b)
{
    __shared__ uint32_t sW[3 * 2304];    // layers 2,3,4
    __shared__ float sP[4][64];
    int b  = blockIdx.x >> 6;
    int n0 = (blockIdx.x & 63) << 6;
    int tid = threadIdx.x, wid = tid >> 5, lane = tid & 31;
    int lr = lane >> 2, lc = lane & 3;
    int row0 = n0 + wid * 16 + lr;

    for (int i = tid; i < 3 * 2304 / 4; i += 128)
        ((uint4*)sW)[i] = ((const uint4*)(d_wT + 2 * 2304))[i];

    uint32_t w[8][2];
    {
        const uint32_t* s0 = d_mu_pool_b16 + (size_t)(b * N_ + row0) * 32;
#pragma unroll
        for (int j = 0; j < 8; j++) {
            w[j][0] = s0[j * 4 + lc];  w[j][1] = s0[8 * 32 + j * 4 + lc];
        }
    }
    __syncthreads();
    float acc[8][4];
    init_bias(acc, postb, lc);      layer_mma(acc, w, sW,            lr, lc); pack_words(acc, w, true);
    init_bias(acc, postb + 64, lc); layer_mma(acc, w, sW + 2304,     lr, lc); pack_words(acc, w, true);
    init_bias(acc, mu2b, lc);       layer_mma(acc, w, sW + 2 * 2304, lr, lc);   // mu2, no relu

    float x0 = xv[b * N_ + row0],      x8  = xv[b * N_ + row0 + 8];
    float m0v = (float)mask[b * N_ + row0],  m8v  = (float)mask[b * N_ + row0 + 8];
    uint32_t* d0 = d_mu_b16 + (size_t)(b * N_ + row0) * 32;

    float ps[8][2];
#pragma unroll
    for (int j = 0; j < 8; j++) {
        int c0 = j * 8 + 2 * lc;
        float u0 = mu1[c0], u1 = mu1[c0 + 1];
        float v00 = fmaxf(fmaxf(x0 * u0, 0.f) * m0v + acc[j][0] * m0v, 0.f);
        float v01 = fmaxf(fmaxf(x0 * u1, 0.f) * m0v + acc[j][1] * m0v, 0.f);
        float v80 = fmaxf(fmaxf(x8 * u0, 0.f) * m8v + acc[j][2] * m8v, 0.f);
        float v81 = fmaxf(fmaxf(x8 * u1, 0.f) * m8v + acc[j][3] * m8v, 0.f);
        d0[j * 4 + lc]          = pack_bf16x2(v00, v01);
        d0[8 * 32 + j * 4 + lc] = pack_bf16x2(v80, v81);
        ps[j][0] = x0 * v00 + x8 * v80;
        ps[j][1] = x0 * v01 + x8 * v81;
    }
#pragma unroll
    for (int j = 0; j < 8; j++) {
#pragma unroll
        for (int h = 0; h < 2; h++) {
            float t = ps[j][h];
            t += __shfl_xor_sync(0xffffffffu, t, 4);
            t += __shfl_xor_sync(0xffffffffu, t, 8);
            t += __shfl_xor_sync(0xffffffffu, t, 16);
            if (lr == 0) sP[wid][j * 8 + 2 * lc + h] = t;
        }
    }
    __syncthreads();
    if (tid < 64)
        d_partial[(b * 64 + (blockIdx.x & 63)) * 64 + tid] =
            sP[0][tid] + sP[1][tid] + sP[2][tid] + sP[3][tid];
}

// ============ kernel 4: q head, 2 m-tiles/warp, parallel prologue ============
__global__ void __launch_bounds__(128) q_kernel(
    const int* __restrict__ mask,
    const float* __restrict__ q1W, const float* __restrict__ q1b,
    const float* __restrict__ qregW, const float* __restrict__ qregb,
    const float* __restrict__ q2b,
    const float* __restrict__ qW, const float* __restrict__ qb,
    float* __restrict__ out)
{
    __shared__ uint32_t sW[2304 + 1152];   // q2 layer + qreg lower half
    __shared__ float pooled[64], q1s[64], c1s[32];
    __shared__ float red[2][64];
    __shared__ float red4[4][32];
    int b  = blockIdx.x >> 5;
    int n0 = (blockIdx.x & 31) << 7;       // 128 nodes per block
    int tid = threadIdx.x, wid = tid >> 5, lane = tid & 31;
    int lr = lane >> 2, lc = lane & 3;

    for (int i = tid; i < (2304 + 1152) / 4; i += 128)
        ((uint4*)sW)[i] = (i < 2304 / 4) ? ((const uint4*)(d_wT + 5 * 2304))[i]
                                         : ((const uint4*)d_wTq)[i - 2304 / 4];

    {   // pooled reduce: 2 groups over t, coalesced in d
        int d = tid & 63, g = tid >> 6;
        float s = 0.f;
#pragma unroll 4
        for (int t = g; t < 64; t += 2) s += d_partial[(b * 64 + t) * 64 + d];
        red[g][d] = s;
    }
    __syncthreads();
    if (tid < 64) pooled[tid] = red[0][tid] + red[1][tid];
    __syncthreads();
    {   // q1 with all 128 threads: 2-way k split
        int d = tid & 63, g = tid >> 6;
        float a = (g == 0) ? q1b[d] : 0.f;
#pragma unroll 8
        for (int k = g * 32; k < g * 32 + 32; k++)
            a = fmaf(pooled[k], q1W[k * 64 + d], a);
        red[g][d] = a;
    }
    __syncthreads();
    if (tid < 64) q1s[tid] = red[0][tid] + red[1][tid];
    __syncthreads();
    {   // c1 with all 128 threads: 4-way k split
        int rh = tid & 31, g = tid >> 5;
        float c = (g == 0) ? qregb[rh] : 0.f;
#pragma unroll 8
        for (int k = g * 16; k < g * 16 + 16; k++)
            c = fmaf(q1s[k], qregW[k * 32 + rh], c);
        red4[g][rh] = c;
    }
    __syncthreads();
    if (tid < 32)
        c1s[tid] = red4[0][tid] + red4[1][tid] + red4[2][tid] + red4[3][tid];
    __syncthreads();

    int row0 = n0 + wid * 32 + lr;
    int row1 = row0 + 16;
    uint32_t w0[8][2], w1[8][2];
    {
        const uint32_t* s0 = d_mu_b16 + (size_t)(b * N_ + row0) * 32;
        const uint32_t* s1 = d_mu_b16 + (size_t)(b * N_ + row1) * 32;
#pragma unroll
        for (int j = 0; j < 8; j++) {
            w0[j][0] = s0[j * 4 + lc];  w0[j][1] = s0[8 * 32 + j * 4 + lc];
            w1[j][0] = s1[j * 4 + lc];  w1[j][1] = s1[8 * 32 + j * 4 + lc];
        }
    }
    float a0[8][4], a1[8][4];
    init_bias(a0, q2b, lc); init_bias(a1, q2b, lc);
    layer_mma2(a0, a1, w0, w1, sW, lr, lc);     // q2 (no relu)
    pack_words(a0, w0, false); pack_words(a1, w1, false);

    // qreg mma: N=32, acc init = c1, both tiles share weight loads
    float qa0[4][4], qa1[4][4];
#pragma unroll
    for (int j = 0; j < 4; j++) {
        int c0 = j * 8 + 2 * lc;
        qa0[j][0] = qa0[j][2] = c1s[c0];
        qa0[j][1] = qa0[j][3] = c1s[c0 + 1];
        qa1[j][0] = qa1[j][2] = c1s[c0];
        qa1[j][1] = qa1[j][3] = c1s[c0 + 1];
    }
    const uint32_t* sQ = sW + 2304;
#pragma unroll
    for (int kt = 0; kt < 4; kt++) {
        uint32_t x0[4] = { w0[2 * kt][0], w0[2 * kt][1], w0[2 * kt + 1][0], w0[2 * kt + 1][1] };
        uint32_t x1[4] = { w1[2 * kt][0], w1[2 * kt][1], w1[2 * kt + 1][0], w1[2 * kt + 1][1] };
#pragma unroll
        for (int j = 0; j < 4; j++) {
            uint32_t bb[2];
            bb[0] = sQ[(j * 8 + lr) * 36 + kt * 8 + lc];
            bb[1] = sQ[(j * 8 + lr) * 36 + kt * 8 + lc + 4];
            mma_bf16(qa0[j], x0, bb);
            mma_bf16(qa1[j], x1, bb);
        }
    }
    float s00 = 0.f, s08 = 0.f, s10 = 0.f, s18 = 0.f;
#pragma unroll
    for (int j = 0; j < 4; j++) {
        int c0 = j * 8 + 2 * lc;
        float wq0 = qW[c0], wq1 = qW[c0 + 1];
        s00 += fmaxf(qa0[j][0], 0.f) * wq0 + fmaxf(qa0[j][1], 0.f) * wq1;
        s08 += fmaxf(qa0[j][2], 0.f) * wq0 + fmaxf(qa0[j][3], 0.f) * wq1;
        s10 += fmaxf(qa1[j][0], 0.f) * wq0 + fmaxf(qa1[j][1], 0.f) * wq1;
        s18 += fmaxf(qa1[j][2], 0.f) * wq0 + fmaxf(qa1[j][3], 0.f) * wq1;
    }
#pragma unroll
    for (int d = 1; d <= 2; d <<= 1) {
        s00 += __shfl_xor_sync(0xffffffffu, s00, d);
        s08 += __shfl_xor_sync(0xffffffffu, s08, d);
        s10 += __shfl_xor_sync(0xffffffffu, s10, d);
        s18 += __shfl_xor_sync(0xffffffffu, s18, d);
    }
    if (lc == 0) {
        float q0 = s00 + qb[0], q8 = s08 + qb[0], q16 = s10 + qb[0], q24 = s18 + qb[0];
        if (mask[b * N_ + row0] == 0)      q0  = -99999.0f;
        if (mask[b * N_ + row0 + 8] == 0)  q8  = -99999.0f;
        if (mask[b * N_ + row1] == 0)      q16 = -99999.0f;
        if (mask[b * N_ + row1 + 8] == 0)  q24 = -99999.0f;
        out[b * N_ + row0]      = q0;
        out[b * N_ + row0 + 8]  = q8;
        out[b * N_ + row1]      = q16;
        out[b * N_ + row1 + 8]  = q24;
    }
}

// ================= launcher =================
extern "C" void kernel_launch(void* const* d_in, const int* in_sizes, int n_in,
                              void* d_out, int out_size) {
    const float* xv    = (const float*)d_in[0];
    const float* adj   = (const float*)d_in[2];   // edges_weight_adj (d_in[1] is the dead 'adj')
    const int*   mask  = (const int*)  d_in[3];
    const float* mu1   = (const float*)d_in[4];
    const float* mu2W  = (const float*)d_in[5];
    const float* mu2b  = (const float*)d_in[6];
    const float* preW  = (const float*)d_in[7];
    const float* preb  = (const float*)d_in[8];
    const float* postW = (const float*)d_in[9];
    const float* postb = (const float*)d_in[10];
    const float* q1W   = (const float*)d_in[11];
    const float* q1b   = (const float*)d_in[12];
    const float* q2W   = (const float*)d_in[13];
    const float* q2b   = (const float*)d_in[14];
    const float* qregW = (const float*)d_in[15];
    const float* qregb = (const float*)d_in[16];
    const float* qW    = (const float*)d_in[17];
    const float* qb    = (const float*)d_in[18];
    float* out = (float*)d_out;

    cudaFuncSetAttribute(gemm_kernel, cudaFuncAttributeMaxDynamicSharedMemorySize, GEMM_SMEM);

    wprep_kernel<<<64, 256>>>(preW, postW, mu2W, q2W, qregW);
    prep_kernel<<<512, 128>>>(xv, mask, mu1, preb);
    gemm_kernel<<<256, 256, GEMM_SMEM>>>(adj, mask);
    post_kernel<<<512, 128>>>(xv, mask, mu1, postb, mu2b);
    q_kernel<<<256, 128>>>(mask, q1W, q1b, qregW, qregb, q2b, qW, qb, out);
}